// round 13
// baseline (speedup 1.0000x reference)
#include <cuda_runtime.h>
#include <cuda_fp16.h>
#include <cstdint>
#include <math.h>

#define BATCH 16
#define CH    512
#define NSP   1024
#define HEADS 4
#define HD    128
#define GROUPS_N 32
#define GSIZE (16*1024)
#define EPSV  1e-5f
#define ATT_SCALE 0.08838834764831845f
// ATT_SCALE * log2(e): Q pre-scale so softmax uses exp2
#define QSC_L2E 0.12751741204555613f

// ---------------------------------------------------------------------------
// Scratch (device globals). fp16 operands; fp32 accumulation.
// ---------------------------------------------------------------------------
__device__ __half g_hth[(size_t)BATCH*NSP*CH];        // GN out [b][n][c]
__device__ __half g_qkh[(size_t)BATCH*NSP*1024];      // Q(scaled),K [b][n][o<1024]
__device__ __half g_vth[(size_t)BATCH*HEADS*HD*NSP];  // V [b,h][d][m]
__device__ __half g_oth[(size_t)BATCH*NSP*CH];        // attn out [b][n][c]
__device__ __half g_wqh[(size_t)(3*CH)*CH];           // fp16 qkv_w
__device__ __half g_wph[(size_t)CH*CH];               // fp16 proj_w

// ---------------------------------------------------------------------------
// Helpers
// ---------------------------------------------------------------------------
__device__ __forceinline__ uint32_t smem_u32(const void* p){
    uint32_t a;
    asm("{ .reg .u64 t; cvta.to.shared.u64 t, %1; cvt.u32.u64 %0, t; }" : "=r"(a) : "l"(p));
    return a;
}
__device__ __forceinline__ void cp16(uint32_t dst, const void* src){
    asm volatile("cp.async.cg.shared.global [%0], [%1], 16;" :: "r"(dst), "l"(src) : "memory");
}
#define CP_COMMIT() asm volatile("cp.async.commit_group;" ::: "memory")
#define CP_WAIT1()  asm volatile("cp.async.wait_group 1;" ::: "memory")
#define CP_WAIT0()  asm volatile("cp.async.wait_group 0;" ::: "memory")

#define MMAH(c, a, b) \
    asm volatile("mma.sync.aligned.m16n8k16.row.col.f32.f16.f16.f32 " \
        "{%0,%1,%2,%3},{%4,%5,%6,%7},{%8,%9},{%0,%1,%2,%3};" \
        : "+f"((c)[0]), "+f"((c)[1]), "+f"((c)[2]), "+f"((c)[3]) \
        : "r"((a)[0]), "r"((a)[1]), "r"((a)[2]), "r"((a)[3]), \
          "r"((b)[0]), "r"((b)[1]))

#define LDSM4(r0, r1, r2, r3, addr) \
    asm volatile("ldmatrix.sync.aligned.m8n8.x4.shared.b16 {%0,%1,%2,%3}, [%4];" \
        : "=r"(r0), "=r"(r1), "=r"(r2), "=r"(r3) : "r"(addr))

__device__ __forceinline__ uint32_t packh2(float lo, float hi){
    __half2 h = __floats2half2_rn(lo, hi);
    return *reinterpret_cast<uint32_t*>(&h);
}

// ---------------------------------------------------------------------------
// Weight convert -> fp16
// ---------------------------------------------------------------------------
__global__ __launch_bounds__(256) void cvtw_kernel(
    const float* __restrict__ qw, const float* __restrict__ pw)
{
    int i = blockIdx.x * 256 + threadIdx.x;
    if (i < 3*CH*CH) g_wqh[i] = __float2half_rn(qw[i]);
    if (i < CH*CH)   g_wph[i] = __float2half_rn(pw[i]);
}

// ---------------------------------------------------------------------------
// GroupNorm + transpose -> g_hth[b][n][c] fp16
// ---------------------------------------------------------------------------
__global__ __launch_bounds__(256) void gn_kernel(
    const float* __restrict__ x,
    const float* __restrict__ nw,
    const float* __restrict__ nb)
{
    __shared__ float t[16][257];
    int bg = blockIdx.x;
    int b = bg >> 5, g = bg & 31;
    const float* xp = x + (size_t)bg * GSIZE;
    int tid = threadIdx.x;

    float s = 0.f, s2 = 0.f;
    for (int i = tid; i < GSIZE; i += 256) { float v = xp[i]; s += v; s2 += v * v; }
    float* rs  = &t[0][0];
    float* rs2 = rs + 1024;
    rs[tid] = s; rs2[tid] = s2;
    __syncthreads();
    for (int o = 128; o > 0; o >>= 1) {
        if (tid < o) { rs[tid] += rs[tid + o]; rs2[tid] += rs2[tid + o]; }
        __syncthreads();
    }
    float mu   = rs[0] * (1.f / GSIZE);
    float var  = rs2[0] * (1.f / GSIZE) - mu * mu;
    float rinv = rsqrtf(var + EPSV);
    __syncthreads();

    int cl = tid & 15;
    float wc = nw[g * 16 + cl] * rinv;
    float bc = nb[g * 16 + cl] - mu * wc;
    __half* hp = g_hth + (size_t)b * NSP * CH + g * 16;

    for (int n0 = 0; n0 < NSP; n0 += 256) {
#pragma unroll
        for (int c = 0; c < 16; c++) t[c][tid] = xp[c * NSP + n0 + tid];
        __syncthreads();
#pragma unroll
        for (int j = 0; j < 16; j++) {
            int nn = (tid >> 4) + j * 16;
            hp[(size_t)(n0 + nn) * CH + cl] = __float2half_rn(t[cl][nn] * wc + bc);
        }
        __syncthreads();
    }
}

// ---------------------------------------------------------------------------
// fp16 mma.sync GEMM with ldmatrix fragment loads (unchanged from R12).
// ---------------------------------------------------------------------------
#define BKH 64
#define HSTR 72
#define HSTRB (HSTR*2)             // 144 bytes
#define TILE_H (128*HSTR)
#define STAGE_H (2*TILE_H)
#define GEMM_SMEM (2*STAGE_H*2)    // 73728 bytes

template<int MODE>
__global__ __launch_bounds__(128, 3) void gemm_tc(
    const float* __restrict__ bias,
    const float* __restrict__ resid, float* __restrict__ outp)
{
    extern __shared__ __half hsm[];
    const int tid = threadIdx.x;
    uint32_t smb = smem_u32(hsm);

    int m0 = blockIdx.x * 128;
    int n0 = blockIdx.y * 128;
    int z  = blockIdx.z;

    const __half *A, *B;
    if (MODE == 0) {
        A = g_hth + ((size_t)z * NSP + m0) * CH;
        B = g_wqh + (size_t)n0 * CH;
    } else {
        A = g_oth + ((size_t)z * NSP + m0) * CH;
        B = g_wph + (size_t)n0 * CH;
    }
    const int lda = CH, ldb = CH;
    const int nch = CH / BKH;   // 8

    const int lane = tid & 31, wid = tid >> 5;
    const int wm = wid & 1, wn = wid >> 1;
    const int g = lane >> 2, t = lane & 3;
    const int rr = tid >> 3, f_ = tid & 7;

    const uint32_t ldA = (uint32_t)(((lane & 7) + ((lane >> 3) & 1) * 8) * HSTRB + (lane >> 4) * 16);
    const uint32_t ldB = (uint32_t)((lane & 7) * HSTRB + ((lane >> 3) & 1) * 16 + (lane >> 4) * 8 * HSTRB);

    float acc[4][8][4];
#pragma unroll
    for (int i = 0; i < 4; i++)
#pragma unroll
        for (int j = 0; j < 8; j++)
#pragma unroll
            for (int q = 0; q < 4; q++) acc[i][j][q] = 0.f;

    auto issue = [&](int ci) {
        int s = ci & 1;
        uint32_t as = smb + (uint32_t)(s * STAGE_H) * 2u;
        uint32_t bs = as + (uint32_t)TILE_H * 2u;
        int k0 = ci * BKH;
#pragma unroll
        for (int it = 0; it < 8; it++) {
            int r = it * 16 + rr;
            cp16(as + (uint32_t)(r * HSTR + f_ * 8) * 2u, A + (size_t)r * lda + k0 + f_ * 8);
            cp16(bs + (uint32_t)(r * HSTR + f_ * 8) * 2u, B + (size_t)r * ldb + k0 + f_ * 8);
        }
    };

    issue(0); CP_COMMIT();

    for (int ci = 0; ci < nch; ci++) {
        if (ci + 1 < nch) { issue(ci + 1); CP_COMMIT(); CP_WAIT1(); }
        else              { CP_WAIT0(); }
        __syncthreads();

        uint32_t As = smb + (uint32_t)((ci & 1) * STAGE_H) * 2u;
        uint32_t Bs = As + (uint32_t)TILE_H * 2u;
        uint32_t aBase = As + (uint32_t)(wm * 64) * HSTRB + ldA;
        uint32_t bBase = Bs + (uint32_t)(wn * 64) * HSTRB + ldB;

        uint32_t a[2][4][4], b[2][8][2];
#pragma unroll
        for (int mt = 0; mt < 4; mt++)
            LDSM4(a[0][mt][0], a[0][mt][1], a[0][mt][2], a[0][mt][3],
                  aBase + (uint32_t)(mt * 16) * HSTRB);
#pragma unroll
        for (int np = 0; np < 4; np++)
            LDSM4(b[0][2*np][0], b[0][2*np][1], b[0][2*np+1][0], b[0][2*np+1][1],
                  bBase + (uint32_t)(np * 16) * HSTRB);

#pragma unroll
        for (int ks = 0; ks < 4; ks++) {
            int cur = ks & 1, nxt = cur ^ 1;
            if (ks < 3) {
                uint32_t ko = (uint32_t)((ks + 1) * 32);
#pragma unroll
                for (int mt = 0; mt < 4; mt++)
                    LDSM4(a[nxt][mt][0], a[nxt][mt][1], a[nxt][mt][2], a[nxt][mt][3],
                          aBase + (uint32_t)(mt * 16) * HSTRB + ko);
#pragma unroll
                for (int np = 0; np < 4; np++)
                    LDSM4(b[nxt][2*np][0], b[nxt][2*np][1], b[nxt][2*np+1][0], b[nxt][2*np+1][1],
                          bBase + (uint32_t)(np * 16) * HSTRB + ko);
            }
#pragma unroll
            for (int mt = 0; mt < 4; mt++)
#pragma unroll
                for (int nt = 0; nt < 8; nt++)
                    MMAH(acc[mt][nt], a[cur][mt], b[cur][nt]);
        }
        __syncthreads();
    }

    float* Ds = (float*)hsm;
#pragma unroll
    for (int mt = 0; mt < 4; mt++)
#pragma unroll
        for (int nt = 0; nt < 8; nt++) {
            int r = wm * 64 + mt * 16 + g;
            int c = wn * 64 + nt * 8 + 2 * t;
            Ds[c * 133 + r]           = acc[mt][nt][0];
            Ds[(c + 1) * 133 + r]     = acc[mt][nt][1];
            Ds[c * 133 + r + 8]       = acc[mt][nt][2];
            Ds[(c + 1) * 133 + r + 8] = acc[mt][nt][3];
        }
    __syncthreads();

    if (MODE == 0) {
        if (n0 < 1024) {
            float sc = (n0 < 512) ? QSC_L2E : 1.f;
#pragma unroll 8
            for (int p = 0; p < 128; p++) {
                int e = p * 128 + tid; int r = e >> 7; int c = e & 127;
                g_qkh[((size_t)z * NSP + m0 + r) * 1024 + n0 + c] =
                    __float2half_rn((Ds[c * 133 + r] + bias[n0 + c]) * sc);
            }
        } else {
            int h = (n0 - 1024) >> 7;
#pragma unroll 8
            for (int p = 0; p < 128; p++) {
                int e = p * 128 + tid; int c = e >> 7; int r = e & 127;
                g_vth[(((size_t)z * HEADS + h) * HD + c) * NSP + m0 + r] =
                    __float2half_rn(Ds[c * 133 + r] + bias[n0 + c]);
            }
        }
    } else {
#pragma unroll 8
        for (int p = 0; p < 128; p++) {
            int e = p * 128 + tid; int c = e >> 7; int r = e & 127;
            size_t off = ((size_t)z * CH + n0 + c) * NSP + m0 + r;
            outp[off] = Ds[c * 133 + r] + bias[n0 + c] + resid[off];
        }
    }
}

// ---------------------------------------------------------------------------
// Fused flash attention, fp16 mma + ldmatrix, DOUBLE-BUFFERED K and V.
// CTA = 128 thr (4 warps), q-tile 64. One barrier + one cp-wait per k-tile:
// iter it issues K_{it+1}/V_{it+1} into the opposite slots at the TOP
// (safe: those slots were last read at it-1; bottom sync of it-1 covers),
// computes S -> softmax -> PV, then CP_WAIT0 + one __syncthreads.
// smem (bytes): Q @0 (17408), K0 @17408, K1 @34816, V0 @52224, V1 @70656.
// Total 89088 -> 2 CTAs/SM. grid = (NSP/64, BATCH*HEADS)
// ---------------------------------------------------------------------------
#define FLH_SMEM 89088
#define QKSTRB 272     // 136 halves
#define VSTRB  144     // 72 halves
#define KOFF0 17408u
#define KOFF1 34816u
#define VOFF0 52224u
#define VOFF1 70656u

__global__ __launch_bounds__(128, 2) void flash_kernel()
{
    extern __shared__ __half hsm[];
    const int tid = threadIdx.x;
    uint32_t smb = smem_u32(hsm);
    const int lane = tid & 31, wid = tid >> 5;
    const int g = lane >> 2, t = lane & 3;

    const uint32_t ldQ = (uint32_t)(((lane & 7) + ((lane >> 3) & 1) * 8) * QKSTRB + (lane >> 4) * 16);
    const uint32_t ldK = (uint32_t)((lane & 7) * QKSTRB + (lane >> 3) * 16);
    const uint32_t ldV = (uint32_t)((lane & 7) * VSTRB  + (lane >> 3) * 16);

    int n0 = blockIdx.x * 64;
    int bh = blockIdx.y;
    int b = bh >> 2, h = bh & 3;
    const __half* qh = g_qkh + (size_t)b * NSP * 1024 + h * HD;
    const __half* kh = qh + 512;
    const __half* vh = g_vth + (size_t)bh * HD * NSP;

    // per-thread staging coords (hoisted)
    const int sr = tid >> 4, sf = tid & 15;     // Q/K tiles: row base, float4 idx
    const int vr = tid >> 3, vf = tid & 7;      // V tiles

    // Prologue: Q -> bufQ, K0 -> K-slot0, V0 -> V-slot0 (one group)
#pragma unroll
    for (int tr = 0; tr < 8; tr++) {
        int r = tr * 8 + sr;
        cp16(smb + (uint32_t)(r * 136 + sf * 8) * 2u, qh + (size_t)(n0 + r) * 1024 + sf * 8);
        cp16(smb + KOFF0 + (uint32_t)(r * 136 + sf * 8) * 2u, kh + (size_t)r * 1024 + sf * 8);
    }
#pragma unroll
    for (int tr = 0; tr < 8; tr++) {
        int d = tr * 16 + vr;
        cp16(smb + VOFF0 + (uint32_t)(d * 72 + vf * 8) * 2u, vh + (size_t)d * NSP + vf * 8);
    }
    CP_COMMIT();
    CP_WAIT0();
    __syncthreads();

    // Q fragments: 8 k16-steps, one ldmatrix.x4 each; persistent (bufQ never reused)
    uint32_t qf[8][4];
    {
        uint32_t qBase = smb + (uint32_t)(wid * 16) * QKSTRB + ldQ;
#pragma unroll
        for (int ks = 0; ks < 8; ks++)
            LDSM4(qf[ks][0], qf[ks][1], qf[ks][2], qf[ks][3], qBase + ks * 32);
    }

    float oacc[16][4];
#pragma unroll
    for (int i = 0; i < 16; i++)
#pragma unroll
        for (int q = 0; q < 4; q++) oacc[i][q] = 0.f;
    float rowm[2] = {-1e30f, -1e30f};
    float rowl[2] = {0.f, 0.f};

    for (int it = 0; it < 16; it++) {
        // top-of-iter prefetch of K_{it+1}/V_{it+1} into the OPPOSITE slots
        if (it + 1 < 16) {
            uint32_t kw = ((it + 1) & 1) ? KOFF1 : KOFF0;
            uint32_t vw = ((it + 1) & 1) ? VOFF1 : VOFF0;
            const __half* kb = kh + (size_t)(it + 1) * 64 * 1024;
            const __half* vb = vh + (it + 1) * 64;
#pragma unroll
            for (int tr = 0; tr < 8; tr++) {
                int r = tr * 8 + sr;
                cp16(smb + kw + (uint32_t)(r * 136 + sf * 8) * 2u, kb + (size_t)r * 1024 + sf * 8);
            }
#pragma unroll
            for (int tr = 0; tr < 8; tr++) {
                int d = tr * 16 + vr;
                cp16(smb + vw + (uint32_t)(d * 72 + vf * 8) * 2u, vb + (size_t)d * NSP + vf * 8);
            }
            CP_COMMIT();
        }

        uint32_t kslot = (it & 1) ? KOFF1 : KOFF0;
        uint32_t vslot = (it & 1) ? VOFF1 : VOFF0;

        // S = Q K^T
        float sacc[8][4];
#pragma unroll
        for (int i = 0; i < 8; i++)
#pragma unroll
            for (int q = 0; q < 4; q++) sacc[i][q] = 0.f;

#pragma unroll
        for (int nt = 0; nt < 8; nt++) {
            uint32_t kaddr = smb + kslot + (uint32_t)(nt * 8) * QKSTRB + ldK;
#pragma unroll
            for (int kp = 0; kp < 4; kp++) {
                uint32_t b0, b1, b2, b3;
                LDSM4(b0, b1, b2, b3, kaddr + kp * 64);
                uint32_t bb0[2] = {b0, b1}, bb1[2] = {b2, b3};
                MMAH(sacc[nt], qf[2 * kp],     bb0);
                MMAH(sacc[nt], qf[2 * kp + 1], bb1);
            }
        }

        // online softmax, log2 domain
        float tm0 = -1e30f, tm1 = -1e30f;
#pragma unroll
        for (int nt = 0; nt < 8; nt++) {
            tm0 = fmaxf(tm0, fmaxf(sacc[nt][0], sacc[nt][1]));
            tm1 = fmaxf(tm1, fmaxf(sacc[nt][2], sacc[nt][3]));
        }
#pragma unroll
        for (int o = 1; o < 4; o <<= 1) {
            tm0 = fmaxf(tm0, __shfl_xor_sync(0xffffffffu, tm0, o));
            tm1 = fmaxf(tm1, __shfl_xor_sync(0xffffffffu, tm1, o));
        }
        float mn0 = fmaxf(rowm[0], tm0), mn1 = fmaxf(rowm[1], tm1);
        float al0 = exp2f(rowm[0] - mn0), al1 = exp2f(rowm[1] - mn1);
        float ts0 = 0.f, ts1 = 0.f;
#pragma unroll
        for (int nt = 0; nt < 8; nt++) {
            sacc[nt][0] = exp2f(sacc[nt][0] - mn0);
            sacc[nt][1] = exp2f(sacc[nt][1] - mn0);
            sacc[nt][2] = exp2f(sacc[nt][2] - mn1);
            sacc[nt][3] = exp2f(sacc[nt][3] - mn1);
            ts0 += sacc[nt][0] + sacc[nt][1];
            ts1 += sacc[nt][2] + sacc[nt][3];
        }
#pragma unroll
        for (int o = 1; o < 4; o <<= 1) {
            ts0 += __shfl_xor_sync(0xffffffffu, ts0, o);
            ts1 += __shfl_xor_sync(0xffffffffu, ts1, o);
        }
        rowl[0] = rowl[0] * al0 + ts0;
        rowl[1] = rowl[1] * al1 + ts1;
        rowm[0] = mn0; rowm[1] = mn1;
#pragma unroll
        for (int nt = 0; nt < 16; nt++) {
            oacc[nt][0] *= al0; oacc[nt][1] *= al0;
            oacc[nt][2] *= al1; oacc[nt][3] *= al1;
        }

        // O += P V^T
#pragma unroll
        for (int kp = 0; kp < 2; kp++) {
            uint32_t pa0[4], pa1[4];
            int k0 = 2 * kp, k1 = 2 * kp + 1;
            pa0[0] = packh2(sacc[2*k0][0],   sacc[2*k0][1]);
            pa0[1] = packh2(sacc[2*k0][2],   sacc[2*k0][3]);
            pa0[2] = packh2(sacc[2*k0+1][0], sacc[2*k0+1][1]);
            pa0[3] = packh2(sacc[2*k0+1][2], sacc[2*k0+1][3]);
            pa1[0] = packh2(sacc[2*k1][0],   sacc[2*k1][1]);
            pa1[1] = packh2(sacc[2*k1][2],   sacc[2*k1][3]);
            pa1[2] = packh2(sacc[2*k1+1][0], sacc[2*k1+1][1]);
            pa1[3] = packh2(sacc[2*k1+1][2], sacc[2*k1+1][3]);
#pragma unroll
            for (int nt = 0; nt < 16; nt++) {
                uint32_t vaddr = smb + vslot + (uint32_t)(nt * 8) * VSTRB + ldV + kp * 64;
                uint32_t b0, b1, b2, b3;
                LDSM4(b0, b1, b2, b3, vaddr);
                uint32_t bb0[2] = {b0, b1}, bb1[2] = {b2, b3};
                MMAH(oacc[nt], pa0, bb0);
                MMAH(oacc[nt], pa1, bb1);
            }
        }

        // single wait + barrier per iteration
        if (it < 15) {
            CP_WAIT0();
            __syncthreads();
        }
    }

    // normalize + direct fp16 stores -> g_oth[b][n][c]
    float inv0 = 1.f / rowl[0], inv1 = 1.f / rowl[1];
    int r = wid * 16 + g;
    __half* ob = g_oth + ((size_t)b * NSP + n0) * CH + h * HD;
#pragma unroll
    for (int nt = 0; nt < 16; nt++) {
        int d = nt * 8 + 2 * t;
        *(uint32_t*)&ob[(size_t)r * CH + d] =
            packh2(oacc[nt][0] * inv0, oacc[nt][1] * inv0);
        *(uint32_t*)&ob[(size_t)(r + 8) * CH + d] =
            packh2(oacc[nt][2] * inv1, oacc[nt][3] * inv1);
    }
}

// ---------------------------------------------------------------------------
// Launch
// ---------------------------------------------------------------------------
extern "C" void kernel_launch(void* const* d_in, const int* in_sizes, int n_in,
                              void* d_out, int out_size)
{
    const float* x      = (const float*)d_in[0];
    const float* norm_w = (const float*)d_in[1];
    const float* norm_b = (const float*)d_in[2];
    const float* qkv_w  = (const float*)d_in[3];
    const float* qkv_b  = (const float*)d_in[4];
    const float* proj_w = (const float*)d_in[5];
    const float* proj_b = (const float*)d_in[6];
    float* out = (float*)d_out;

    cudaFuncSetAttribute(gemm_tc<0>, cudaFuncAttributeMaxDynamicSharedMemorySize, GEMM_SMEM);
    cudaFuncSetAttribute(gemm_tc<3>, cudaFuncAttributeMaxDynamicSharedMemorySize, GEMM_SMEM);
    cudaFuncSetAttribute(flash_kernel, cudaFuncAttributeMaxDynamicSharedMemorySize, FLH_SMEM);

    cvtw_kernel<<<(3 * CH * CH + 255) / 256, 256>>>(qkv_w, proj_w);
    gn_kernel<<<BATCH * GROUPS_N, 256>>>(x, norm_w, norm_b);

    gemm_tc<0><<<dim3(NSP / 128, 1536 / 128, BATCH), 128, GEMM_SMEM>>>(qkv_b, nullptr, nullptr);
    flash_kernel<<<dim3(NSP / 64, BATCH * HEADS), 128, FLH_SMEM>>>();
    gemm_tc<3><<<dim3(NSP / 128, CH / 128, BATCH), 128, GEMM_SMEM>>>(proj_b, x, out);
}

// round 14
// speedup vs baseline: 1.0394x; 1.0394x over previous
#include <cuda_runtime.h>
#include <cuda_fp16.h>
#include <cstdint>
#include <math.h>

#define BATCH 16
#define CH    512
#define NSP   1024
#define HEADS 4
#define HD    128
#define GROUPS_N 32
#define GSIZE (16*1024)
#define EPSV  1e-5f
#define ATT_SCALE 0.08838834764831845f
// ATT_SCALE * log2(e): Q pre-scale so softmax uses exp2
#define QSC_L2E 0.12751741204555613f

// ---------------------------------------------------------------------------
// Scratch (device globals). fp16 operands; fp32 accumulation in GEMMs.
// ---------------------------------------------------------------------------
__device__ __half g_hth[(size_t)BATCH*NSP*CH];        // GN out [b][n][c]
__device__ __half g_qkh[(size_t)BATCH*NSP*1024];      // Q(scaled),K [b][n][o<1024]
__device__ __half g_vth[(size_t)BATCH*HEADS*HD*NSP];  // V [b,h][d][m]
__device__ __half g_oth[(size_t)BATCH*NSP*CH];        // attn out [b][n][c]
__device__ __half g_wqh[(size_t)(3*CH)*CH];           // fp16 qkv_w
__device__ __half g_wph[(size_t)CH*CH];               // fp16 proj_w

// ---------------------------------------------------------------------------
// Helpers
// ---------------------------------------------------------------------------
__device__ __forceinline__ uint32_t smem_u32(const void* p){
    uint32_t a;
    asm("{ .reg .u64 t; cvta.to.shared.u64 t, %1; cvt.u32.u64 %0, t; }" : "=r"(a) : "l"(p));
    return a;
}
__device__ __forceinline__ void cp16(uint32_t dst, const void* src){
    asm volatile("cp.async.cg.shared.global [%0], [%1], 16;" :: "r"(dst), "l"(src) : "memory");
}
#define CP_COMMIT() asm volatile("cp.async.commit_group;" ::: "memory")
#define CP_WAIT1()  asm volatile("cp.async.wait_group 1;" ::: "memory")
#define CP_WAIT0()  asm volatile("cp.async.wait_group 0;" ::: "memory")

// fp16 in, fp32 acc (GEMMs)
#define MMAH(c, a, b) \
    asm volatile("mma.sync.aligned.m16n8k16.row.col.f32.f16.f16.f32 " \
        "{%0,%1,%2,%3},{%4,%5,%6,%7},{%8,%9},{%0,%1,%2,%3};" \
        : "+f"((c)[0]), "+f"((c)[1]), "+f"((c)[2]), "+f"((c)[3]) \
        : "r"((a)[0]), "r"((a)[1]), "r"((a)[2]), "r"((a)[3]), \
          "r"((b)[0]), "r"((b)[1]))

// fp16 in, fp16 acc (flash) — C/D are 2 regs of half2
#define MMAH16(c, a, b) \
    asm volatile("mma.sync.aligned.m16n8k16.row.col.f16.f16.f16.f16 " \
        "{%0,%1},{%2,%3,%4,%5},{%6,%7},{%0,%1};" \
        : "+r"((c)[0]), "+r"((c)[1]) \
        : "r"((a)[0]), "r"((a)[1]), "r"((a)[2]), "r"((a)[3]), \
          "r"((b)[0]), "r"((b)[1]))

#define LDSM4(r0, r1, r2, r3, addr) \
    asm volatile("ldmatrix.sync.aligned.m8n8.x4.shared.b16 {%0,%1,%2,%3}, [%4];" \
        : "=r"(r0), "=r"(r1), "=r"(r2), "=r"(r3) : "r"(addr))

__device__ __forceinline__ uint32_t packh2(float lo, float hi){
    __half2 h = __floats2half2_rn(lo, hi);
    return *reinterpret_cast<uint32_t*>(&h);
}
__device__ __forceinline__ float2 unpackh2(uint32_t v){
    __half2 h = *reinterpret_cast<__half2*>(&v);
    return __half22float2(h);
}
__device__ __forceinline__ uint32_t hmul2u(uint32_t v, uint32_t s){
    __half2 a = *reinterpret_cast<__half2*>(&v);
    __half2 b = *reinterpret_cast<__half2*>(&s);
    __half2 r = __hmul2(a, b);
    return *reinterpret_cast<uint32_t*>(&r);
}

// ---------------------------------------------------------------------------
// Weight convert -> fp16
// ---------------------------------------------------------------------------
__global__ __launch_bounds__(256) void cvtw_kernel(
    const float* __restrict__ qw, const float* __restrict__ pw)
{
    int i = blockIdx.x * 256 + threadIdx.x;
    if (i < 3*CH*CH) g_wqh[i] = __float2half_rn(qw[i]);
    if (i < CH*CH)   g_wph[i] = __float2half_rn(pw[i]);
}

// ---------------------------------------------------------------------------
// GroupNorm + transpose -> g_hth[b][n][c] fp16
// ---------------------------------------------------------------------------
__global__ __launch_bounds__(256) void gn_kernel(
    const float* __restrict__ x,
    const float* __restrict__ nw,
    const float* __restrict__ nb)
{
    __shared__ float t[16][257];
    int bg = blockIdx.x;
    int b = bg >> 5, g = bg & 31;
    const float* xp = x + (size_t)bg * GSIZE;
    int tid = threadIdx.x;

    float s = 0.f, s2 = 0.f;
    for (int i = tid; i < GSIZE; i += 256) { float v = xp[i]; s += v; s2 += v * v; }
    float* rs  = &t[0][0];
    float* rs2 = rs + 1024;
    rs[tid] = s; rs2[tid] = s2;
    __syncthreads();
    for (int o = 128; o > 0; o >>= 1) {
        if (tid < o) { rs[tid] += rs[tid + o]; rs2[tid] += rs2[tid + o]; }
        __syncthreads();
    }
    float mu   = rs[0] * (1.f / GSIZE);
    float var  = rs2[0] * (1.f / GSIZE) - mu * mu;
    float rinv = rsqrtf(var + EPSV);
    __syncthreads();

    int cl = tid & 15;
    float wc = nw[g * 16 + cl] * rinv;
    float bc = nb[g * 16 + cl] - mu * wc;
    __half* hp = g_hth + (size_t)b * NSP * CH + g * 16;

    for (int n0 = 0; n0 < NSP; n0 += 256) {
#pragma unroll
        for (int c = 0; c < 16; c++) t[c][tid] = xp[c * NSP + n0 + tid];
        __syncthreads();
#pragma unroll
        for (int j = 0; j < 16; j++) {
            int nn = (tid >> 4) + j * 16;
            hp[(size_t)(n0 + nn) * CH + cl] = __float2half_rn(t[cl][nn] * wc + bc);
        }
        __syncthreads();
    }
}

// ---------------------------------------------------------------------------
// fp16 mma.sync GEMM with ldmatrix fragment loads (unchanged from R12).
// ---------------------------------------------------------------------------
#define BKH 64
#define HSTR 72
#define HSTRB (HSTR*2)             // 144 bytes
#define TILE_H (128*HSTR)
#define STAGE_H (2*TILE_H)
#define GEMM_SMEM (2*STAGE_H*2)    // 73728 bytes

template<int MODE>
__global__ __launch_bounds__(128, 3) void gemm_tc(
    const float* __restrict__ bias,
    const float* __restrict__ resid, float* __restrict__ outp)
{
    extern __shared__ __half hsm[];
    const int tid = threadIdx.x;
    uint32_t smb = smem_u32(hsm);

    int m0 = blockIdx.x * 128;
    int n0 = blockIdx.y * 128;
    int z  = blockIdx.z;

    const __half *A, *B;
    if (MODE == 0) {
        A = g_hth + ((size_t)z * NSP + m0) * CH;
        B = g_wqh + (size_t)n0 * CH;
    } else {
        A = g_oth + ((size_t)z * NSP + m0) * CH;
        B = g_wph + (size_t)n0 * CH;
    }
    const int lda = CH, ldb = CH;
    const int nch = CH / BKH;   // 8

    const int lane = tid & 31, wid = tid >> 5;
    const int wm = wid & 1, wn = wid >> 1;
    const int g = lane >> 2, t = lane & 3;
    const int rr = tid >> 3, f_ = tid & 7;

    const uint32_t ldA = (uint32_t)(((lane & 7) + ((lane >> 3) & 1) * 8) * HSTRB + (lane >> 4) * 16);
    const uint32_t ldB = (uint32_t)((lane & 7) * HSTRB + ((lane >> 3) & 1) * 16 + (lane >> 4) * 8 * HSTRB);

    float acc[4][8][4];
#pragma unroll
    for (int i = 0; i < 4; i++)
#pragma unroll
        for (int j = 0; j < 8; j++)
#pragma unroll
            for (int q = 0; q < 4; q++) acc[i][j][q] = 0.f;

    auto issue = [&](int ci) {
        int s = ci & 1;
        uint32_t as = smb + (uint32_t)(s * STAGE_H) * 2u;
        uint32_t bs = as + (uint32_t)TILE_H * 2u;
        int k0 = ci * BKH;
#pragma unroll
        for (int it = 0; it < 8; it++) {
            int r = it * 16 + rr;
            cp16(as + (uint32_t)(r * HSTR + f_ * 8) * 2u, A + (size_t)r * lda + k0 + f_ * 8);
            cp16(bs + (uint32_t)(r * HSTR + f_ * 8) * 2u, B + (size_t)r * ldb + k0 + f_ * 8);
        }
    };

    issue(0); CP_COMMIT();

    for (int ci = 0; ci < nch; ci++) {
        if (ci + 1 < nch) { issue(ci + 1); CP_COMMIT(); CP_WAIT1(); }
        else              { CP_WAIT0(); }
        __syncthreads();

        uint32_t As = smb + (uint32_t)((ci & 1) * STAGE_H) * 2u;
        uint32_t Bs = As + (uint32_t)TILE_H * 2u;
        uint32_t aBase = As + (uint32_t)(wm * 64) * HSTRB + ldA;
        uint32_t bBase = Bs + (uint32_t)(wn * 64) * HSTRB + ldB;

        uint32_t a[2][4][4], b[2][8][2];
#pragma unroll
        for (int mt = 0; mt < 4; mt++)
            LDSM4(a[0][mt][0], a[0][mt][1], a[0][mt][2], a[0][mt][3],
                  aBase + (uint32_t)(mt * 16) * HSTRB);
#pragma unroll
        for (int np = 0; np < 4; np++)
            LDSM4(b[0][2*np][0], b[0][2*np][1], b[0][2*np+1][0], b[0][2*np+1][1],
                  bBase + (uint32_t)(np * 16) * HSTRB);

#pragma unroll
        for (int ks = 0; ks < 4; ks++) {
            int cur = ks & 1, nxt = cur ^ 1;
            if (ks < 3) {
                uint32_t ko = (uint32_t)((ks + 1) * 32);
#pragma unroll
                for (int mt = 0; mt < 4; mt++)
                    LDSM4(a[nxt][mt][0], a[nxt][mt][1], a[nxt][mt][2], a[nxt][mt][3],
                          aBase + (uint32_t)(mt * 16) * HSTRB + ko);
#pragma unroll
                for (int np = 0; np < 4; np++)
                    LDSM4(b[nxt][2*np][0], b[nxt][2*np][1], b[nxt][2*np+1][0], b[nxt][2*np+1][1],
                          bBase + (uint32_t)(np * 16) * HSTRB + ko);
            }
#pragma unroll
            for (int mt = 0; mt < 4; mt++)
#pragma unroll
                for (int nt = 0; nt < 8; nt++)
                    MMAH(acc[mt][nt], a[cur][mt], b[cur][nt]);
        }
        __syncthreads();
    }

    float* Ds = (float*)hsm;
#pragma unroll
    for (int mt = 0; mt < 4; mt++)
#pragma unroll
        for (int nt = 0; nt < 8; nt++) {
            int r = wm * 64 + mt * 16 + g;
            int c = wn * 64 + nt * 8 + 2 * t;
            Ds[c * 133 + r]           = acc[mt][nt][0];
            Ds[(c + 1) * 133 + r]     = acc[mt][nt][1];
            Ds[c * 133 + r + 8]       = acc[mt][nt][2];
            Ds[(c + 1) * 133 + r + 8] = acc[mt][nt][3];
        }
    __syncthreads();

    if (MODE == 0) {
        if (n0 < 1024) {
            float sc = (n0 < 512) ? QSC_L2E : 1.f;
#pragma unroll 8
            for (int p = 0; p < 128; p++) {
                int e = p * 128 + tid; int r = e >> 7; int c = e & 127;
                g_qkh[((size_t)z * NSP + m0 + r) * 1024 + n0 + c] =
                    __float2half_rn((Ds[c * 133 + r] + bias[n0 + c]) * sc);
            }
        } else {
            int h = (n0 - 1024) >> 7;
#pragma unroll 8
            for (int p = 0; p < 128; p++) {
                int e = p * 128 + tid; int c = e >> 7; int r = e & 127;
                g_vth[(((size_t)z * HEADS + h) * HD + c) * NSP + m0 + r] =
                    __float2half_rn(Ds[c * 133 + r] + bias[n0 + c]);
            }
        }
    } else {
#pragma unroll 8
        for (int p = 0; p < 128; p++) {
            int e = p * 128 + tid; int c = e >> 7; int r = e & 127;
            size_t off = ((size_t)z * CH + n0 + c) * NSP + m0 + r;
            outp[off] = Ds[c * 133 + r] + bias[n0 + c] + resid[off];
        }
    }
}

// ---------------------------------------------------------------------------
// Fused flash attention, fp16 mma with FP16 ACCUMULATORS + ldmatrix.
// CTA = 128 thr (4 warps), q-tile 64; each warp owns 16 q-rows.
// Q fragments persistent in registers; Q's smem slot is REUSED as K-slot-0
// after extraction (Q read exactly once). Double-buffered K and V;
// one cp-wait + one barrier per k-tile.
// smem (bytes): Kslot0/Q @0 (17408), Kslot1 @17408, V0 @34816, V1 @53248.
// Total 71680 -> 3 CTAs/SM (12 warps). grid = (NSP/64, BATCH*HEADS)
// K_it lives in slot (it&1)? 0 : 1  (K0 -> slot1; K1 overwrites Q in slot0).
// ---------------------------------------------------------------------------
#define FLH_SMEM 71680
#define QKSTRB 272     // 136 halves
#define VSTRB  144     // 72 halves
#define KOFFA 0u
#define KOFFB 17408u
#define VOFF0 34816u
#define VOFF1 53248u

__global__ __launch_bounds__(128, 3) void flash_kernel()
{
    extern __shared__ __half hsm[];
    const int tid = threadIdx.x;
    uint32_t smb = smem_u32(hsm);
    const int lane = tid & 31, wid = tid >> 5;
    const int g = lane >> 2, t = lane & 3;

    const uint32_t ldQ = (uint32_t)(((lane & 7) + ((lane >> 3) & 1) * 8) * QKSTRB + (lane >> 4) * 16);
    const uint32_t ldK = (uint32_t)((lane & 7) * QKSTRB + (lane >> 3) * 16);
    const uint32_t ldV = (uint32_t)((lane & 7) * VSTRB  + (lane >> 3) * 16);

    int n0 = blockIdx.x * 64;
    int bh = blockIdx.y;
    int b = bh >> 2, h = bh & 3;
    const __half* qh = g_qkh + (size_t)b * NSP * 1024 + h * HD;
    const __half* kh = qh + 512;
    const __half* vh = g_vth + (size_t)bh * HD * NSP;

    const int sr = tid >> 4, sf = tid & 15;     // Q/K staging coords
    const int vr = tid >> 3, vf = tid & 7;      // V staging coords

    // Prologue: Q -> slot0, K0 -> slot1, V0 -> VOFF0
#pragma unroll
    for (int tr = 0; tr < 8; tr++) {
        int r = tr * 8 + sr;
        cp16(smb + KOFFA + (uint32_t)(r * 136 + sf * 8) * 2u, qh + (size_t)(n0 + r) * 1024 + sf * 8);
        cp16(smb + KOFFB + (uint32_t)(r * 136 + sf * 8) * 2u, kh + (size_t)r * 1024 + sf * 8);
    }
#pragma unroll
    for (int tr = 0; tr < 8; tr++) {
        int d = tr * 16 + vr;
        cp16(smb + VOFF0 + (uint32_t)(d * 72 + vf * 8) * 2u, vh + (size_t)d * NSP + vf * 8);
    }
    CP_COMMIT();
    CP_WAIT0();
    __syncthreads();

    // Q fragments: 8 k16-steps, persistent
    uint32_t qf[8][4];
    {
        uint32_t qBase = smb + KOFFA + (uint32_t)(wid * 16) * QKSTRB + ldQ;
#pragma unroll
        for (int ks = 0; ks < 8; ks++)
            LDSM4(qf[ks][0], qf[ks][1], qf[ks][2], qf[ks][3], qBase + ks * 32);
    }
    __syncthreads();     // all warps done with Q before K1 overwrites slot0

    // fp16 accumulators for O: [nt][j]; j=0 rows g, j=1 rows g+8 (half2 pairs)
    uint32_t oacc[16][2];
#pragma unroll
    for (int i = 0; i < 16; i++) { oacc[i][0] = 0u; oacc[i][1] = 0u; }
    float rowm[2] = {-1e30f, -1e30f};
    float rowl[2] = {0.f, 0.f};

    for (int it = 0; it < 16; it++) {
        // top-of-iter prefetch of K_{it+1}/V_{it+1}
        if (it + 1 < 16) {
            uint32_t kw = ((it + 1) & 1) ? KOFFA : KOFFB;
            uint32_t vw = ((it + 1) & 1) ? VOFF1 : VOFF0;
            const __half* kb = kh + (size_t)(it + 1) * 64 * 1024;
            const __half* vb = vh + (it + 1) * 64;
#pragma unroll
            for (int tr = 0; tr < 8; tr++) {
                int r = tr * 8 + sr;
                cp16(smb + kw + (uint32_t)(r * 136 + sf * 8) * 2u, kb + (size_t)r * 1024 + sf * 8);
            }
#pragma unroll
            for (int tr = 0; tr < 8; tr++) {
                int d = tr * 16 + vr;
                cp16(smb + vw + (uint32_t)(d * 72 + vf * 8) * 2u, vb + (size_t)d * NSP + vf * 8);
            }
            CP_COMMIT();
        }

        uint32_t kslot = (it & 1) ? KOFFA : KOFFB;
        uint32_t vslot = (it & 1) ? VOFF1 : VOFF0;

        // S = Q K^T with fp16 accumulation
        uint32_t sacc[8][2];
#pragma unroll
        for (int i = 0; i < 8; i++) { sacc[i][0] = 0u; sacc[i][1] = 0u; }

#pragma unroll
        for (int nt = 0; nt < 8; nt++) {
            uint32_t kaddr = smb + kslot + (uint32_t)(nt * 8) * QKSTRB + ldK;
#pragma unroll
            for (int kp = 0; kp < 4; kp++) {
                uint32_t b0, b1, b2, b3;
                LDSM4(b0, b1, b2, b3, kaddr + kp * 64);
                uint32_t bb0[2] = {b0, b1}, bb1[2] = {b2, b3};
                MMAH16(sacc[nt], qf[2 * kp],     bb0);
                MMAH16(sacc[nt], qf[2 * kp + 1], bb1);
            }
        }

        // unpack logits to fp32
        float p[8][4];
#pragma unroll
        for (int nt = 0; nt < 8; nt++) {
            float2 lo = unpackh2(sacc[nt][0]);
            float2 hi = unpackh2(sacc[nt][1]);
            p[nt][0] = lo.x; p[nt][1] = lo.y;
            p[nt][2] = hi.x; p[nt][3] = hi.y;
        }

        // online softmax, log2 domain
        float tm0 = -1e30f, tm1 = -1e30f;
#pragma unroll
        for (int nt = 0; nt < 8; nt++) {
            tm0 = fmaxf(tm0, fmaxf(p[nt][0], p[nt][1]));
            tm1 = fmaxf(tm1, fmaxf(p[nt][2], p[nt][3]));
        }
#pragma unroll
        for (int o = 1; o < 4; o <<= 1) {
            tm0 = fmaxf(tm0, __shfl_xor_sync(0xffffffffu, tm0, o));
            tm1 = fmaxf(tm1, __shfl_xor_sync(0xffffffffu, tm1, o));
        }
        float mn0 = fmaxf(rowm[0], tm0), mn1 = fmaxf(rowm[1], tm1);
        float al0 = exp2f(rowm[0] - mn0), al1 = exp2f(rowm[1] - mn1);
        float ts0 = 0.f, ts1 = 0.f;
#pragma unroll
        for (int nt = 0; nt < 8; nt++) {
            p[nt][0] = exp2f(p[nt][0] - mn0);
            p[nt][1] = exp2f(p[nt][1] - mn0);
            p[nt][2] = exp2f(p[nt][2] - mn1);
            p[nt][3] = exp2f(p[nt][3] - mn1);
            ts0 += p[nt][0] + p[nt][1];
            ts1 += p[nt][2] + p[nt][3];
        }
#pragma unroll
        for (int o = 1; o < 4; o <<= 1) {
            ts0 += __shfl_xor_sync(0xffffffffu, ts0, o);
            ts1 += __shfl_xor_sync(0xffffffffu, ts1, o);
        }
        rowl[0] = rowl[0] * al0 + ts0;
        rowl[1] = rowl[1] * al1 + ts1;
        rowm[0] = mn0; rowm[1] = mn1;

        // rescale fp16 O accumulators (half2 multiplies)
        uint32_t A0 = packh2(al0, al0), A1 = packh2(al1, al1);
#pragma unroll
        for (int nt = 0; nt < 16; nt++) {
            oacc[nt][0] = hmul2u(oacc[nt][0], A0);
            oacc[nt][1] = hmul2u(oacc[nt][1], A1);
        }

        // O += P V^T with fp16 accumulation
#pragma unroll
        for (int kp = 0; kp < 2; kp++) {
            uint32_t pa0[4], pa1[4];
            int k0 = 2 * kp, k1 = 2 * kp + 1;
            pa0[0] = packh2(p[2*k0][0],   p[2*k0][1]);
            pa0[1] = packh2(p[2*k0][2],   p[2*k0][3]);
            pa0[2] = packh2(p[2*k0+1][0], p[2*k0+1][1]);
            pa0[3] = packh2(p[2*k0+1][2], p[2*k0+1][3]);
            pa1[0] = packh2(p[2*k1][0],   p[2*k1][1]);
            pa1[1] = packh2(p[2*k1][2],   p[2*k1][3]);
            pa1[2] = packh2(p[2*k1+1][0], p[2*k1+1][1]);
            pa1[3] = packh2(p[2*k1+1][2], p[2*k1+1][3]);
#pragma unroll
            for (int nt = 0; nt < 16; nt++) {
                uint32_t vaddr = smb + vslot + (uint32_t)(nt * 8) * VSTRB + ldV + kp * 64;
                uint32_t b0, b1, b2, b3;
                LDSM4(b0, b1, b2, b3, vaddr);
                uint32_t bb0[2] = {b0, b1}, bb1[2] = {b2, b3};
                MMAH16(oacc[nt], pa0, bb0);
                MMAH16(oacc[nt], pa1, bb1);
            }
        }

        // single wait + barrier per iteration
        CP_WAIT0();
        __syncthreads();
    }

    // normalize (fp32) + fp16 stores -> g_oth[b][n][c]
    float inv0 = 1.f / rowl[0], inv1 = 1.f / rowl[1];
    int r = wid * 16 + g;
    __half* ob = g_oth + ((size_t)b * NSP + n0) * CH + h * HD;
#pragma unroll
    for (int nt = 0; nt < 16; nt++) {
        int d = nt * 8 + 2 * t;
        float2 v0 = unpackh2(oacc[nt][0]);
        float2 v1 = unpackh2(oacc[nt][1]);
        *(uint32_t*)&ob[(size_t)r * CH + d]       = packh2(v0.x * inv0, v0.y * inv0);
        *(uint32_t*)&ob[(size_t)(r + 8) * CH + d] = packh2(v1.x * inv1, v1.y * inv1);
    }
}

// ---------------------------------------------------------------------------
// Launch
// ---------------------------------------------------------------------------
extern "C" void kernel_launch(void* const* d_in, const int* in_sizes, int n_in,
                              void* d_out, int out_size)
{
    const float* x      = (const float*)d_in[0];
    const float* norm_w = (const float*)d_in[1];
    const float* norm_b = (const float*)d_in[2];
    const float* qkv_w  = (const float*)d_in[3];
    const float* qkv_b  = (const float*)d_in[4];
    const float* proj_w = (const float*)d_in[5];
    const float* proj_b = (const float*)d_in[6];
    float* out = (float*)d_out;

    cudaFuncSetAttribute(gemm_tc<0>, cudaFuncAttributeMaxDynamicSharedMemorySize, GEMM_SMEM);
    cudaFuncSetAttribute(gemm_tc<3>, cudaFuncAttributeMaxDynamicSharedMemorySize, GEMM_SMEM);
    cudaFuncSetAttribute(flash_kernel, cudaFuncAttributeMaxDynamicSharedMemorySize, FLH_SMEM);

    cvtw_kernel<<<(3 * CH * CH + 255) / 256, 256>>>(qkv_w, proj_w);
    gn_kernel<<<BATCH * GROUPS_N, 256>>>(x, norm_w, norm_b);

    gemm_tc<0><<<dim3(NSP / 128, 1536 / 128, BATCH), 128, GEMM_SMEM>>>(qkv_b, nullptr, nullptr);
    flash_kernel<<<dim3(NSP / 64, BATCH * HEADS), 128, FLH_SMEM>>>();
    gemm_tc<3><<<dim3(NSP / 128, CH / 128, BATCH), 128, GEMM_SMEM>>>(proj_b, x, out);
}